// round 1
// baseline (speedup 1.0000x reference)
#include <cuda_runtime.h>

// Problem constants (fixed by dataset): B=4, H=8, N=4096, R=D=64
#define B_     4
#define H_     8
#define N_     4096
#define R_     64
#define BH_    32
#define CH_    8        // chunks along N for the rank-reduction GEMMs
#define CROWS_ 512      // rows per chunk (N_/CH_)
#define NEG_BIG 3.0e38f

// ---------------- device scratch (static: no allocations allowed) ----------
__device__ float g_pm[BH_*CH_*R_];                    // partial col max
__device__ float g_ps[BH_*CH_*R_];                    // partial col expsum
__device__ float g_m [BH_*R_];                        // final col max
__device__ float g_inv[BH_*R_];                       // 1 / col expsum
__device__ float g_pKV[(size_t)BH_*CH_*R_*R_];        // partial K^T V
__device__ float g_pKK[(size_t)BH_*CH_*R_*R_];        // partial K^T K
__device__ float g_pQQ[(size_t)BH_*CH_*R_*R_];        // partial Q^T Q
__device__ float g_KtV[(size_t)BH_*R_*R_];            // reduced K^T V
__device__ float g_sQ[BH_];                           // sum |Q^TQ - I| per bh
__device__ float g_sK[BH_];                           // sum |K^TK - I| per bh

// ============================================================================
// KS1: per-(bh, chunk) column max and exp-sum of (svd_V + mask bias) over N
// grid (32, 8), 256 threads. tid%64 = column r, tid/64 = row group (4 groups)
// ============================================================================
__global__ void __launch_bounds__(256) svda_ks1(const float* __restrict__ sv,
                                                const float* __restrict__ mask) {
    const int bh = blockIdx.x, c = blockIdx.y;
    const int b  = bh >> 3;
    const int tid = threadIdx.x;
    const int r = tid & 63, g = tid >> 6;                 // g in 0..3
    const float* base = sv + ((size_t)bh * N_ + (size_t)c * CROWS_) * R_;
    const float* mk   = mask + (size_t)b * N_ + (size_t)c * CROWS_;

    __shared__ float sred[4][64];

    // pass 1: max
    float m = -NEG_BIG;
    for (int i = g; i < CROWS_; i += 4) {
        float x = base[(size_t)i * R_ + r] - 1e9f * (1.0f - mk[i]);
        m = fmaxf(m, x);
    }
    sred[g][r] = m;
    __syncthreads();
    if (g == 0) {
        m = fmaxf(fmaxf(sred[0][r], sred[1][r]), fmaxf(sred[2][r], sred[3][r]));
        sred[0][r] = m;
    }
    __syncthreads();
    m = sred[0][r];
    __syncthreads();

    // pass 2: exp-sum (chunk is 128KB -> L1/L2 resident on second pass)
    float s = 0.0f;
    for (int i = g; i < CROWS_; i += 4) {
        float x = base[(size_t)i * R_ + r] - 1e9f * (1.0f - mk[i]);
        s += __expf(x - m);
    }
    sred[g][r] = s;
    __syncthreads();
    if (g == 0) {
        s = sred[0][r] + sred[1][r] + sred[2][r] + sred[3][r];
        g_pm[(bh * CH_ + c) * R_ + r] = m;
        g_ps[(bh * CH_ + c) * R_ + r] = s;
    }
}

// ============================================================================
// KS2: combine chunk partials into final column max and 1/sum. grid 32, 64 thr
// ============================================================================
__global__ void svda_ks2() {
    const int bh = blockIdx.x;
    const int r  = threadIdx.x;
    float m = -NEG_BIG;
    #pragma unroll
    for (int c = 0; c < CH_; c++) m = fmaxf(m, g_pm[(bh * CH_ + c) * R_ + r]);
    float s = 0.0f;
    #pragma unroll
    for (int c = 0; c < CH_; c++)
        s += g_ps[(bh * CH_ + c) * R_ + r] * __expf(g_pm[(bh * CH_ + c) * R_ + r] - m);
    g_m[bh * R_ + r]   = m;
    g_inv[bh * R_ + r] = 1.0f / s;
}

// ============================================================================
// K2: per-(bh, chunk) partial 64x64 reductions over 512 rows:
//     K^T V, K^T K, Q^T Q.  K and Q (softmaxes) computed on the fly.
// grid (32, 8), 256 threads, each thread owns a 4x4 tile of each output.
// ============================================================================
__global__ void __launch_bounds__(256, 2) svda_k2(const float* __restrict__ U,
                                                  const float* __restrict__ sv,
                                                  const float* __restrict__ V,
                                                  const float* __restrict__ mask) {
    const int bh = blockIdx.x, c = blockIdx.y;
    const int b  = bh >> 3;
    const int tid = threadIdx.x;
    const int ty = tid >> 4, tx = tid & 15;       // also (row-in-tile, lane-in-row)
    const int ty4 = ty * 4, tx4 = tx * 4;

    __shared__ float Ksh[16][64];
    __shared__ float Vsh[16][64];
    __shared__ float Qsh[16][64];

    float accKV[4][4] = {}, accKK[4][4] = {}, accQQ[4][4] = {};

    const size_t off = ((size_t)bh * N_ + (size_t)c * CROWS_) * R_;
    const float* Ub = U  + off;
    const float* Sb = sv + off;
    const float* Vb = V  + off;
    const float* mk = mask + (size_t)b * N_ + (size_t)c * CROWS_;

    // per-thread column stats for this thread's fixed 4 columns (r = tx4..tx4+3)
    const float4 m4 = *(const float4*)&g_m  [bh * R_ + tx4];
    const float4 i4 = *(const float4*)&g_inv[bh * R_ + tx4];

    for (int t = 0; t < CROWS_ / 16; t++) {
        const int row = t * 16 + ty;                  // row within chunk
        const size_t ro = (size_t)row * R_ + tx4;

        // --- Q: row softmax of U over 64, 16 lanes cooperate per row ---
        float4 u = *(const float4*)&Ub[ro];
        float mx = fmaxf(fmaxf(u.x, u.y), fmaxf(u.z, u.w));
        #pragma unroll
        for (int d = 1; d < 16; d <<= 1) mx = fmaxf(mx, __shfl_xor_sync(0xffffffffu, mx, d));
        float4 e;
        e.x = __expf(u.x - mx); e.y = __expf(u.y - mx);
        e.z = __expf(u.z - mx); e.w = __expf(u.w - mx);
        float sm = e.x + e.y + e.z + e.w;
        #pragma unroll
        for (int d = 1; d < 16; d <<= 1) sm += __shfl_xor_sync(0xffffffffu, sm, d);
        const float qinv = 1.0f / sm;
        *(float4*)&Qsh[ty][tx4] = make_float4(e.x * qinv, e.y * qinv, e.z * qinv, e.w * qinv);

        // --- K: column softmax value exp(x - m[r]) / s[r] ---
        float4 s = *(const float4*)&Sb[ro];
        const float bias = -1e9f * (1.0f - mk[row]);
        float4 kv;
        kv.x = __expf(s.x + bias - m4.x) * i4.x;
        kv.y = __expf(s.y + bias - m4.y) * i4.y;
        kv.z = __expf(s.z + bias - m4.z) * i4.z;
        kv.w = __expf(s.w + bias - m4.w) * i4.w;
        *(float4*)&Ksh[ty][tx4] = kv;

        // --- V: straight copy ---
        *(float4*)&Vsh[ty][tx4] = *(const float4*)&Vb[ro];

        __syncthreads();

        #pragma unroll
        for (int kk = 0; kk < 16; kk++) {
            const float4 ka4 = *(const float4*)&Ksh[kk][ty4];
            const float4 qa4 = *(const float4*)&Qsh[kk][ty4];
            const float4 kb4 = *(const float4*)&Ksh[kk][tx4];
            const float4 qb4 = *(const float4*)&Qsh[kk][tx4];
            const float4 vb4 = *(const float4*)&Vsh[kk][tx4];
            const float ka[4] = {ka4.x, ka4.y, ka4.z, ka4.w};
            const float qa[4] = {qa4.x, qa4.y, qa4.z, qa4.w};
            const float kb[4] = {kb4.x, kb4.y, kb4.z, kb4.w};
            const float qb[4] = {qb4.x, qb4.y, qb4.z, qb4.w};
            const float vb[4] = {vb4.x, vb4.y, vb4.z, vb4.w};
            #pragma unroll
            for (int i = 0; i < 4; i++)
                #pragma unroll
                for (int j = 0; j < 4; j++) {
                    accKV[i][j] = fmaf(ka[i], vb[j], accKV[i][j]);
                    accKK[i][j] = fmaf(ka[i], kb[j], accKK[i][j]);
                    accQQ[i][j] = fmaf(qa[i], qb[j], accQQ[i][j]);
                }
        }
        __syncthreads();
    }

    // write partials (deterministic reduce in next kernel, no atomics)
    const size_t pbase = (size_t)(bh * CH_ + c) * R_ * R_;
    #pragma unroll
    for (int i = 0; i < 4; i++) {
        const size_t o = pbase + (size_t)(ty4 + i) * R_ + tx4;
        *(float4*)&g_pKV[o] = make_float4(accKV[i][0], accKV[i][1], accKV[i][2], accKV[i][3]);
        *(float4*)&g_pKK[o] = make_float4(accKK[i][0], accKK[i][1], accKK[i][2], accKK[i][3]);
        *(float4*)&g_pQQ[o] = make_float4(accQQ[i][0], accQQ[i][1], accQQ[i][2], accQQ[i][3]);
    }
}

// ============================================================================
// R1: reduce chunk partials -> g_KtV; compute sum|Q^TQ-I|, sum|K^TK-I| per bh
// grid 32, 256 threads
// ============================================================================
__global__ void __launch_bounds__(256) svda_r1() {
    const int bh = blockIdx.x;
    const int tid = threadIdx.x;
    float aQ = 0.0f, aK = 0.0f;
    for (int e = tid; e < R_ * R_; e += 256) {
        const int i = e >> 6, j = e & 63;
        float skv = 0.0f, skk = 0.0f, sqq = 0.0f;
        #pragma unroll
        for (int c = 0; c < CH_; c++) {
            const size_t o = (size_t)(bh * CH_ + c) * R_ * R_ + e;
            skv += g_pKV[o]; skk += g_pKK[o]; sqq += g_pQQ[o];
        }
        g_KtV[(size_t)bh * R_ * R_ + e] = skv;
        const float eye = (i == j) ? 1.0f : 0.0f;
        aQ += fabsf(sqq - eye);
        aK += fabsf(skk - eye);
    }
    __shared__ float rQ[256], rK[256];
    rQ[tid] = aQ; rK[tid] = aK;
    __syncthreads();
    for (int st = 128; st > 0; st >>= 1) {
        if (tid < st) { rQ[tid] += rQ[tid + st]; rK[tid] += rK[tid + st]; }
        __syncthreads();
    }
    if (tid == 0) { g_sQ[bh] = rQ[0]; g_sK[bh] = rK[0]; }
}

// ============================================================================
// R2: finalize ortho_loss[b] = REG*mean|symQ| + REG*mean|symK|
// ============================================================================
__global__ void svda_r2(float* __restrict__ out) {
    const int b = threadIdx.x;
    if (b < B_) {
        float s = 0.0f;
        #pragma unroll
        for (int h = 0; h < H_; h++) s += g_sQ[b * H_ + h] + g_sK[b * H_ + h];
        out[(size_t)BH_ * N_ * R_ + b] = 0.1f * s / (float)(H_ * R_ * R_);
    }
}

// ============================================================================
// K3: X = (softmax_r(U) * graph_filter) @ KtV, per (bh, 64-row block)
// grid (32, 64), 256 threads; 4x4 output microtiles.
// ============================================================================
__global__ void __launch_bounds__(256) svda_k3(const float* __restrict__ U,
                                               const float* __restrict__ Sigma,
                                               const float* __restrict__ gammas,
                                               int ng,
                                               float* __restrict__ X) {
    const int bh = blockIdx.x, cb = blockIdx.y;
    const int tid = threadIdx.x;

    __shared__ float Qf[64 * 68];     // [row][r], pitch 68 (16B-aligned rows)
    __shared__ float Kt[64 * 64];     // KtV [r][d]
    __shared__ float filt[64];

    // graph filter: Horner(sigmoid(Sigma))
    if (tid < 64) {
        const float x  = Sigma[bh * R_ + tid];
        const float sg = 1.0f / (1.0f + __expf(-x));
        float o = gammas[ng - 1];
        for (int k = ng - 2; k >= 0; k--) o = fmaf(o, sg, gammas[k]);
        filt[tid] = o;
    }
    // load KtV tile
    for (int e = tid * 4; e < R_ * R_; e += 1024)
        *(float4*)&Kt[e] = *(const float4*)&g_KtV[(size_t)bh * R_ * R_ + e];
    __syncthreads();

    // Qf = softmax_r(U row) * filt ; 4 lanes cooperate per row (16 elems each)
    {
        const int row = tid >> 2, lane = tid & 3;
        const float* ur = U + ((size_t)bh * N_ + (size_t)cb * 64 + row) * R_ + lane * 16;
        float4 u[4];
        #pragma unroll
        for (int q = 0; q < 4; q++) u[q] = *(const float4*)(ur + q * 4);
        float mx = -NEG_BIG;
        #pragma unroll
        for (int q = 0; q < 4; q++)
            mx = fmaxf(mx, fmaxf(fmaxf(u[q].x, u[q].y), fmaxf(u[q].z, u[q].w)));
        #pragma unroll
        for (int d = 1; d < 4; d <<= 1) mx = fmaxf(mx, __shfl_xor_sync(0xffffffffu, mx, d));
        float4 e[4];
        float sm = 0.0f;
        #pragma unroll
        for (int q = 0; q < 4; q++) {
            e[q].x = __expf(u[q].x - mx); e[q].y = __expf(u[q].y - mx);
            e[q].z = __expf(u[q].z - mx); e[q].w = __expf(u[q].w - mx);
            sm += e[q].x + e[q].y + e[q].z + e[q].w;
        }
        #pragma unroll
        for (int d = 1; d < 4; d <<= 1) sm += __shfl_xor_sync(0xffffffffu, sm, d);
        const float inv = 1.0f / sm;
        #pragma unroll
        for (int q = 0; q < 4; q++) {
            const int r = lane * 16 + q * 4;
            float4 o;
            o.x = e[q].x * inv * filt[r + 0];
            o.y = e[q].y * inv * filt[r + 1];
            o.z = e[q].z * inv * filt[r + 2];
            o.w = e[q].w * inv * filt[r + 3];
            *(float4*)&Qf[row * 68 + r] = o;
        }
    }
    __syncthreads();

    // GEMM: [64 x 64] = Qf[64 x 64] @ Kt[64 x 64]
    const int ty = tid >> 4, tx = tid & 15;
    float acc[4][4] = {};
    #pragma unroll
    for (int k = 0; k < 64; k += 4) {
        float4 a[4], bb[4];
        #pragma unroll
        for (int i = 0; i < 4; i++) a[i]  = *(const float4*)&Qf[(ty * 4 + i) * 68 + k];
        #pragma unroll
        for (int kk = 0; kk < 4; kk++) bb[kk] = *(const float4*)&Kt[(k + kk) * 64 + tx * 4];
        #pragma unroll
        for (int i = 0; i < 4; i++) {
            const float av[4] = {a[i].x, a[i].y, a[i].z, a[i].w};
            #pragma unroll
            for (int kk = 0; kk < 4; kk++) {
                acc[i][0] = fmaf(av[kk], bb[kk].x, acc[i][0]);
                acc[i][1] = fmaf(av[kk], bb[kk].y, acc[i][1]);
                acc[i][2] = fmaf(av[kk], bb[kk].z, acc[i][2]);
                acc[i][3] = fmaf(av[kk], bb[kk].w, acc[i][3]);
            }
        }
    }
    #pragma unroll
    for (int i = 0; i < 4; i++) {
        const size_t o = ((size_t)bh * N_ + (size_t)cb * 64 + ty * 4 + i) * R_ + tx * 4;
        *(float4*)&X[o] = make_float4(acc[i][0], acc[i][1], acc[i][2], acc[i][3]);
    }
}

// ============================================================================
// launcher
// inputs: 0:U 1:Sigma 2:svd_V 3:V 4:mask 5:gammas ; output: X (8388608) + loss(4)
// ============================================================================
extern "C" void kernel_launch(void* const* d_in, const int* in_sizes, int n_in,
                              void* d_out, int out_size) {
    const float* U      = (const float*)d_in[0];
    const float* Sigma  = (const float*)d_in[1];
    const float* svd_V  = (const float*)d_in[2];
    const float* V      = (const float*)d_in[3];
    const float* mask   = (const float*)d_in[4];
    const float* gammas = (const float*)d_in[5];
    const int ng = in_sizes[5];
    float* out = (float*)d_out;

    svda_ks1<<<dim3(BH_, CH_), 256>>>(svd_V, mask);
    svda_ks2<<<BH_, 64>>>();
    svda_k2 <<<dim3(BH_, CH_), 256>>>(U, svd_V, V, mask);
    svda_r1 <<<BH_, 256>>>();
    svda_r2 <<<1, 32>>>(out);
    svda_k3 <<<dim3(BH_, N_ / 64), 256>>>(U, Sigma, gammas, ng, out);
}

// round 2
// speedup vs baseline: 1.1981x; 1.1981x over previous
#include <cuda_runtime.h>

// Problem constants (fixed by dataset): B=4, H=8, N=4096, R=D=64
#define B_     4
#define H_     8
#define N_     4096
#define R_     64
#define BH_    32
#define CH_    16       // chunks along N for the rank-reduction GEMMs
#define CROWS_ 256      // rows per chunk (N_/CH_)
#define EB_    8        // r1 element-blocks
#define NEG_BIG 3.0e38f

typedef unsigned long long ull;

// ---------------- f32x2 packed-math helpers (sm_100+ PTX only) -------------
__device__ __forceinline__ ull dup2(float x) {
    ull r;
    asm("mov.b64 %0, {%1, %2};" : "=l"(r) : "r"(__float_as_uint(x)), "r"(__float_as_uint(x)));
    return r;
}
__device__ __forceinline__ void fma2(ull& d, ull a, ull b) {
    asm("fma.rn.f32x2 %0, %1, %2, %0;" : "+l"(d) : "l"(a), "l"(b));
}
__device__ __forceinline__ void up2(ull v, float& lo, float& hi) {
    unsigned int a, b;
    asm("mov.b64 {%0, %1}, %2;" : "=r"(a), "=r"(b) : "l"(v));
    lo = __uint_as_float(a); hi = __uint_as_float(b);
}

// ---------------- device scratch (static: no allocations allowed) ----------
__device__ float g_pm[BH_*CH_*R_];                    // partial col max
__device__ float g_ps[BH_*CH_*R_];                    // partial col expsum
__device__ float g_m [BH_*R_];                        // final col max
__device__ float g_inv[BH_*R_];                       // 1 / col expsum
__device__ float g_pKV[(size_t)BH_*CH_*R_*R_];        // partial K^T V
__device__ float g_pKK[(size_t)BH_*CH_*R_*R_];        // partial K^T K
__device__ float g_pQQ[(size_t)BH_*CH_*R_*R_];        // partial Q^T Q
__device__ float g_KtV[(size_t)BH_*R_*R_];            // reduced K^T V
__device__ float g_sQp[BH_*EB_];                      // partial sum |Q^TQ - I|
__device__ float g_sKp[BH_*EB_];                      // partial sum |K^TK - I|

// ============================================================================
// KS1: per-(bh, chunk) column max and exp-sum of (svd_V + mask bias) over N
// grid (32, 16), 256 threads. tid%64 = column r, tid/64 = row group
// ============================================================================
__global__ void __launch_bounds__(256) svda_ks1(const float* __restrict__ sv,
                                                const float* __restrict__ mask) {
    const int bh = blockIdx.x, c = blockIdx.y;
    const int b  = bh >> 3;
    const int tid = threadIdx.x;
    const int r = tid & 63, g = tid >> 6;                 // g in 0..3
    const float* base = sv + ((size_t)bh * N_ + (size_t)c * CROWS_) * R_;
    const float* mk   = mask + (size_t)b * N_ + (size_t)c * CROWS_;

    __shared__ float sred[4][64];

    float m = -NEG_BIG;
    for (int i = g; i < CROWS_; i += 4) {
        float x = base[(size_t)i * R_ + r] - 1e9f * (1.0f - mk[i]);
        m = fmaxf(m, x);
    }
    sred[g][r] = m;
    __syncthreads();
    if (g == 0) {
        m = fmaxf(fmaxf(sred[0][r], sred[1][r]), fmaxf(sred[2][r], sred[3][r]));
        sred[0][r] = m;
    }
    __syncthreads();
    m = sred[0][r];
    __syncthreads();

    float s = 0.0f;
    for (int i = g; i < CROWS_; i += 4) {
        float x = base[(size_t)i * R_ + r] - 1e9f * (1.0f - mk[i]);
        s += __expf(x - m);
    }
    sred[g][r] = s;
    __syncthreads();
    if (g == 0) {
        s = sred[0][r] + sred[1][r] + sred[2][r] + sred[3][r];
        g_pm[(bh * CH_ + c) * R_ + r] = m;
        g_ps[(bh * CH_ + c) * R_ + r] = s;
    }
}

// ============================================================================
// KS2: combine chunk partials into final column max and 1/sum. grid 32, 64 thr
// ============================================================================
__global__ void svda_ks2() {
    const int bh = blockIdx.x;
    const int r  = threadIdx.x;
    float m = -NEG_BIG;
    #pragma unroll
    for (int c = 0; c < CH_; c++) m = fmaxf(m, g_pm[(bh * CH_ + c) * R_ + r]);
    float s = 0.0f;
    #pragma unroll
    for (int c = 0; c < CH_; c++)
        s += g_ps[(bh * CH_ + c) * R_ + r] * __expf(g_pm[(bh * CH_ + c) * R_ + r] - m);
    g_m[bh * R_ + r]   = m;
    g_inv[bh * R_ + r] = 1.0f / s;
}

// ============================================================================
// K2: per-(bh, chunk) partial 64x64 reductions over 256 rows:
//     K^T V, K^T K, Q^T Q.  K and Q (softmaxes) computed on the fly.
// grid (32, 16), 128 threads. 8x4 microtile per thread, f32x2 packed FMAs.
// ============================================================================
__global__ void __launch_bounds__(128) svda_k2(const float* __restrict__ U,
                                               const float* __restrict__ sv,
                                               const float* __restrict__ V,
                                               const float* __restrict__ mask) {
    const int bh = blockIdx.x, c = blockIdx.y;
    const int b  = bh >> 3;
    const int tid = threadIdx.x;
    // loader mapping: row lr (0..15), 8-col strip lc
    const int lr = tid >> 3;
    const int lc = (tid & 7) * 8;
    // compute mapping: 8-row strip (4 pairs) x 4 cols
    const int ty8 = (tid >> 4) * 8;
    const int tx4 = (tid & 15) * 4;

    __shared__ float Ksh[16][64];
    __shared__ float Qsh[16][64];
    __shared__ float Vsh[16][64];

    const size_t off = ((size_t)bh * N_ + (size_t)c * CROWS_) * R_;
    const float* Ub = U  + off;
    const float* Sb = sv + off;
    const float* Vb = V  + off;
    const float* mk = mask + (size_t)b * N_ + (size_t)c * CROWS_;

    // column-softmax stats for this thread's 8 loader columns
    const float4 mA = *(const float4*)&g_m  [bh * R_ + lc];
    const float4 mB = *(const float4*)&g_m  [bh * R_ + lc + 4];
    const float4 iA = *(const float4*)&g_inv[bh * R_ + lc];
    const float4 iB = *(const float4*)&g_inv[bh * R_ + lc + 4];

    ull aKV[4][4], aKK[4][4], aQQ[4][4];
    #pragma unroll
    for (int i = 0; i < 4; i++)
        #pragma unroll
        for (int j = 0; j < 4; j++) { aKV[i][j] = 0ull; aKK[i][j] = 0ull; aQQ[i][j] = 0ull; }

    // prefetch tile 0
    size_t pidx = (size_t)lr * R_ + lc;
    float4 u0 = *(const float4*)&Ub[pidx], u1 = *(const float4*)&Ub[pidx + 4];
    float4 s0 = *(const float4*)&Sb[pidx], s1 = *(const float4*)&Sb[pidx + 4];
    float4 v0 = *(const float4*)&Vb[pidx], v1 = *(const float4*)&Vb[pidx + 4];
    float mk0 = mk[lr];

    for (int t = 0; t < CROWS_ / 16; t++) {
        // ---- Q: row softmax over 64 (8 lanes cooperate per row) ----
        float mx = fmaxf(fmaxf(fmaxf(u0.x, u0.y), fmaxf(u0.z, u0.w)),
                         fmaxf(fmaxf(u1.x, u1.y), fmaxf(u1.z, u1.w)));
        #pragma unroll
        for (int d = 1; d < 8; d <<= 1) mx = fmaxf(mx, __shfl_xor_sync(0xffffffffu, mx, d));
        float4 e0, e1;
        e0.x = __expf(u0.x - mx); e0.y = __expf(u0.y - mx);
        e0.z = __expf(u0.z - mx); e0.w = __expf(u0.w - mx);
        e1.x = __expf(u1.x - mx); e1.y = __expf(u1.y - mx);
        e1.z = __expf(u1.z - mx); e1.w = __expf(u1.w - mx);
        float sm = e0.x + e0.y + e0.z + e0.w + e1.x + e1.y + e1.z + e1.w;
        #pragma unroll
        for (int d = 1; d < 8; d <<= 1) sm += __shfl_xor_sync(0xffffffffu, sm, d);
        const float qiv = 1.0f / sm;
        *(float4*)&Qsh[lr][lc]     = make_float4(e0.x*qiv, e0.y*qiv, e0.z*qiv, e0.w*qiv);
        *(float4*)&Qsh[lr][lc + 4] = make_float4(e1.x*qiv, e1.y*qiv, e1.z*qiv, e1.w*qiv);

        // ---- K: column softmax exp(x - m[r]) / s[r] ----
        const float bias = -1e9f * (1.0f - mk0);
        float4 k0, k1;
        k0.x = __expf(s0.x + bias - mA.x) * iA.x;
        k0.y = __expf(s0.y + bias - mA.y) * iA.y;
        k0.z = __expf(s0.z + bias - mA.z) * iA.z;
        k0.w = __expf(s0.w + bias - mA.w) * iA.w;
        k1.x = __expf(s1.x + bias - mB.x) * iB.x;
        k1.y = __expf(s1.y + bias - mB.y) * iB.y;
        k1.z = __expf(s1.z + bias - mB.z) * iB.z;
        k1.w = __expf(s1.w + bias - mB.w) * iB.w;
        *(float4*)&Ksh[lr][lc]     = k0;
        *(float4*)&Ksh[lr][lc + 4] = k1;
        *(float4*)&Vsh[lr][lc]     = v0;
        *(float4*)&Vsh[lr][lc + 4] = v1;
        __syncthreads();

        // prefetch next tile (lands during the FMA loop below)
        if (t < CROWS_ / 16 - 1) {
            pidx = (size_t)((t + 1) * 16 + lr) * R_ + lc;
            u0 = *(const float4*)&Ub[pidx]; u1 = *(const float4*)&Ub[pidx + 4];
            s0 = *(const float4*)&Sb[pidx]; s1 = *(const float4*)&Sb[pidx + 4];
            v0 = *(const float4*)&Vb[pidx]; v1 = *(const float4*)&Vb[pidx + 4];
            mk0 = mk[(t + 1) * 16 + lr];
        }

        #pragma unroll
        for (int kk = 0; kk < 16; kk++) {
            const ulonglong2 kaA = *(const ulonglong2*)&Ksh[kk][ty8];
            const ulonglong2 kaB = *(const ulonglong2*)&Ksh[kk][ty8 + 4];
            const ulonglong2 qaA = *(const ulonglong2*)&Qsh[kk][ty8];
            const ulonglong2 qaB = *(const ulonglong2*)&Qsh[kk][ty8 + 4];
            const ull ka[4] = {kaA.x, kaA.y, kaB.x, kaB.y};
            const ull qa[4] = {qaA.x, qaA.y, qaB.x, qaB.y};
            const float4 kb = *(const float4*)&Ksh[kk][tx4];
            const float4 qb = *(const float4*)&Qsh[kk][tx4];
            const float4 vb = *(const float4*)&Vsh[kk][tx4];
            const ull kbd[4] = {dup2(kb.x), dup2(kb.y), dup2(kb.z), dup2(kb.w)};
            const ull qbd[4] = {dup2(qb.x), dup2(qb.y), dup2(qb.z), dup2(qb.w)};
            const ull vbd[4] = {dup2(vb.x), dup2(vb.y), dup2(vb.z), dup2(vb.w)};
            #pragma unroll
            for (int ip = 0; ip < 4; ip++)
                #pragma unroll
                for (int j = 0; j < 4; j++) {
                    fma2(aKV[ip][j], ka[ip], vbd[j]);
                    fma2(aKK[ip][j], ka[ip], kbd[j]);
                    fma2(aQQ[ip][j], qa[ip], qbd[j]);
                }
        }
        __syncthreads();
    }

    // write partials (deterministic reduce in next kernel, no atomics)
    const size_t pbase = (size_t)(bh * CH_ + c) * R_ * R_;
    #pragma unroll
    for (int ip = 0; ip < 4; ip++) {
        float l0, h0, l1, h1, l2, h2, l3, h3;
        const size_t o0 = pbase + (size_t)(ty8 + 2*ip)     * R_ + tx4;
        const size_t o1 = pbase + (size_t)(ty8 + 2*ip + 1) * R_ + tx4;
        up2(aKV[ip][0], l0, h0); up2(aKV[ip][1], l1, h1);
        up2(aKV[ip][2], l2, h2); up2(aKV[ip][3], l3, h3);
        *(float4*)&g_pKV[o0] = make_float4(l0, l1, l2, l3);
        *(float4*)&g_pKV[o1] = make_float4(h0, h1, h2, h3);
        up2(aKK[ip][0], l0, h0); up2(aKK[ip][1], l1, h1);
        up2(aKK[ip][2], l2, h2); up2(aKK[ip][3], l3, h3);
        *(float4*)&g_pKK[o0] = make_float4(l0, l1, l2, l3);
        *(float4*)&g_pKK[o1] = make_float4(h0, h1, h2, h3);
        up2(aQQ[ip][0], l0, h0); up2(aQQ[ip][1], l1, h1);
        up2(aQQ[ip][2], l2, h2); up2(aQQ[ip][3], l3, h3);
        *(float4*)&g_pQQ[o0] = make_float4(l0, l1, l2, l3);
        *(float4*)&g_pQQ[o1] = make_float4(h0, h1, h2, h3);
    }
}

// ============================================================================
// R1: reduce chunk partials -> g_KtV; partial sums of |Q^TQ-I|, |K^TK-I|
// grid (32, 8), 128 threads — 256 blocks (was 32: the 31us occupancy hole)
// ============================================================================
__global__ void __launch_bounds__(128) svda_r1() {
    const int bh = blockIdx.x, eb = blockIdx.y;
    const int tid = threadIdx.x;
    float aQ = 0.0f, aK = 0.0f;
    #pragma unroll
    for (int ee = 0; ee < 4; ee++) {
        const int e = eb * 512 + ee * 128 + tid;
        const int i = e >> 6, j = e & 63;
        float skv = 0.0f, skk = 0.0f, sqq = 0.0f;
        #pragma unroll
        for (int cc = 0; cc < CH_; cc++) {
            const size_t o = (size_t)(bh * CH_ + cc) * R_ * R_ + e;
            skv += g_pKV[o]; skk += g_pKK[o]; sqq += g_pQQ[o];
        }
        g_KtV[(size_t)bh * R_ * R_ + e] = skv;
        const float eye = (i == j) ? 1.0f : 0.0f;
        aQ += fabsf(sqq - eye);
        aK += fabsf(skk - eye);
    }
    __shared__ float rQ[128], rK[128];
    rQ[tid] = aQ; rK[tid] = aK;
    __syncthreads();
    for (int st = 64; st > 0; st >>= 1) {
        if (tid < st) { rQ[tid] += rQ[tid + st]; rK[tid] += rK[tid + st]; }
        __syncthreads();
    }
    if (tid == 0) { g_sQp[bh * EB_ + eb] = rQ[0]; g_sKp[bh * EB_ + eb] = rK[0]; }
}

// ============================================================================
// R2: finalize ortho_loss[b]
// ============================================================================
__global__ void svda_r2(float* __restrict__ out) {
    const int tid = threadIdx.x;
    __shared__ float sm[BH_];
    if (tid < BH_) {
        float s = 0.0f;
        #pragma unroll
        for (int eb = 0; eb < EB_; eb++)
            s += g_sQp[tid * EB_ + eb] + g_sKp[tid * EB_ + eb];
        sm[tid] = s;
    }
    __syncthreads();
    if (tid < B_) {
        float s = 0.0f;
        #pragma unroll
        for (int h = 0; h < H_; h++) s += sm[tid * H_ + h];
        out[(size_t)BH_ * N_ * R_ + tid] = 0.1f * s / (float)(H_ * R_ * R_);
    }
}

// ============================================================================
// K3: X = (softmax_r(U) * graph_filter) @ KtV
// grid (32, 64), 64 threads. 8x8 microtile per thread, f32x2 packed FMAs.
// ============================================================================
__global__ void __launch_bounds__(64) svda_k3(const float* __restrict__ U,
                                              const float* __restrict__ Sigma,
                                              const float* __restrict__ gammas,
                                              int ng,
                                              float* __restrict__ X) {
    const int bh = blockIdx.x, cb = blockIdx.y;
    const int tid = threadIdx.x;

    __shared__ float QfT[64 * 68];    // transposed: [k=r][row], pitch 68
    __shared__ float Kt[64 * 64];     // KtV [r][d]
    __shared__ float filt[64];

    // graph filter: Horner(sigmoid(Sigma))
    {
        const float x  = Sigma[bh * R_ + tid];
        const float sg = 1.0f / (1.0f + __expf(-x));
        float o = gammas[ng - 1];
        for (int k = ng - 2; k >= 0; k--) o = fmaf(o, sg, gammas[k]);
        filt[tid] = o;
    }
    // load KtV tile
    #pragma unroll
    for (int e = tid * 4; e < R_ * R_; e += 256)
        *(float4*)&Kt[e] = *(const float4*)&g_KtV[(size_t)bh * R_ * R_ + e];
    __syncthreads();

    // Qf^T: thread tid owns row tid; serial softmax over 64 then scaled store
    {
        const float* ur = U + ((size_t)bh * N_ + (size_t)cb * 64 + tid) * R_;
        float u[64];
        #pragma unroll
        for (int q = 0; q < 16; q++) {
            const float4 t4 = *(const float4*)(ur + q * 4);
            u[q*4+0] = t4.x; u[q*4+1] = t4.y; u[q*4+2] = t4.z; u[q*4+3] = t4.w;
        }
        float mx = u[0];
        #pragma unroll
        for (int r = 1; r < 64; r++) mx = fmaxf(mx, u[r]);
        float sm = 0.0f;
        #pragma unroll
        for (int r = 0; r < 64; r++) { u[r] = __expf(u[r] - mx); sm += u[r]; }
        const float inv = 1.0f / sm;
        #pragma unroll
        for (int r = 0; r < 64; r++)
            QfT[r * 68 + tid] = u[r] * inv * filt[r];
    }
    __syncthreads();

    // GEMM: X[64x64] = Qf[64x64] @ Kt[64x64]; thread tile 8 rows x 8 cols
    const int ty8 = (tid >> 3) * 8;
    const int jc  = (tid & 7) * 8;
    ull acc[4][8];
    #pragma unroll
    for (int ip = 0; ip < 4; ip++)
        #pragma unroll
        for (int jj = 0; jj < 8; jj++) acc[ip][jj] = 0ull;

    #pragma unroll 4
    for (int kk = 0; kk < 64; kk++) {
        const ulonglong2 aA = *(const ulonglong2*)&QfT[kk * 68 + ty8];
        const ulonglong2 aB = *(const ulonglong2*)&QfT[kk * 68 + ty8 + 4];
        const ull a[4] = {aA.x, aA.y, aB.x, aB.y};
        const float4 b0 = *(const float4*)&Kt[kk * 64 + jc];
        const float4 b1 = *(const float4*)&Kt[kk * 64 + jc + 4];
        const ull bd[8] = {dup2(b0.x), dup2(b0.y), dup2(b0.z), dup2(b0.w),
                           dup2(b1.x), dup2(b1.y), dup2(b1.z), dup2(b1.w)};
        #pragma unroll
        for (int ip = 0; ip < 4; ip++)
            #pragma unroll
            for (int jj = 0; jj < 8; jj++)
                fma2(acc[ip][jj], a[ip], bd[jj]);
    }

    #pragma unroll
    for (int ip = 0; ip < 4; ip++) {
        float lo[8], hi[8];
        #pragma unroll
        for (int jj = 0; jj < 8; jj++) up2(acc[ip][jj], lo[jj], hi[jj]);
        const size_t ro = ((size_t)bh * N_ + (size_t)cb * 64 + ty8 + 2*ip) * R_ + jc;
        *(float4*)&X[ro]          = make_float4(lo[0], lo[1], lo[2], lo[3]);
        *(float4*)&X[ro + 4]      = make_float4(lo[4], lo[5], lo[6], lo[7]);
        *(float4*)&X[ro + R_]     = make_float4(hi[0], hi[1], hi[2], hi[3]);
        *(float4*)&X[ro + R_ + 4] = make_float4(hi[4], hi[5], hi[6], hi[7]);
    }
}

// ============================================================================
// launcher
// inputs: 0:U 1:Sigma 2:svd_V 3:V 4:mask 5:gammas ; output: X (8388608) + loss(4)
// ============================================================================
extern "C" void kernel_launch(void* const* d_in, const int* in_sizes, int n_in,
                              void* d_out, int out_size) {
    const float* U      = (const float*)d_in[0];
    const float* Sigma  = (const float*)d_in[1];
    const float* svd_V  = (const float*)d_in[2];
    const float* V      = (const float*)d_in[3];
    const float* mask   = (const float*)d_in[4];
    const float* gammas = (const float*)d_in[5];
    const int ng = in_sizes[5];
    float* out = (float*)d_out;

    svda_ks1<<<dim3(BH_, CH_), 256>>>(svd_V, mask);
    svda_ks2<<<BH_, 64>>>();
    svda_k2 <<<dim3(BH_, CH_), 128>>>(U, svd_V, V, mask);
    svda_r1 <<<dim3(BH_, EB_), 128>>>();
    svda_r2 <<<1, 32>>>(out);
    svda_k3 <<<dim3(BH_, N_ / 64), 64>>>(U, Sigma, gammas, ng, out);
}